// round 7
// baseline (speedup 1.0000x reference)
#include <cuda_runtime.h>
#include <cuda_bf16.h>

#define BB 8
#define QQ 2048
#define GG 128
#define CC 512
#define KCAND 144
#define FULLM 0xffffffffu

// ---------------- global scratch ----------------
__device__ float g_costT[BB * GG * QQ];                    // [b][g][q]
__device__ unsigned long long g_cand[BB * GG * KCAND];     // sorted (val,idx) per row
__device__ int g_lab[BB * GG];
__device__ int g_n[BB];

// ---------------------------------------------------------------------------
// Detect int64 vs int32 labels/nactual; convert to int32 scratch.
// ---------------------------------------------------------------------------
__global__ void prep_kernel(const void* __restrict__ lab, const void* __restrict__ na) {
    __shared__ int s_bad;
    int t = threadIdx.x;
    if (t == 0) s_bad = 0;
    __syncthreads();
    if (t < 512) {
        long long v = ((const long long*)lab)[t];
        if (v < 0 || v >= CC) s_bad = 1;   // benign race, same value
    }
    __syncthreads();
    if (s_bad == 0) {
        if (t < BB * GG) g_lab[t] = (int)((const long long*)lab)[t];
        if (t < BB)      g_n[t]   = (int)((const long long*)na)[t];
    } else {
        if (t < BB * GG) g_lab[t] = ((const int*)lab)[t];
        if (t < BB)      g_n[t]   = ((const int*)na)[t];
    }
}

// ---------------------------------------------------------------------------
__global__ void cost_kernel(const float* __restrict__ sem,
                            const float* __restrict__ cen,
                            const float* __restrict__ siz,
                            const float* __restrict__ gio,
                            float* __restrict__ outCost) {
    int tid  = blockIdx.x * blockDim.x + threadIdx.x;
    int base = tid << 2;
    if (base >= BB * QQ * GG) return;
    int g  = base & (GG - 1);
    int bq = base >> 7;
    int b  = bq >> 11;

    float4 c4 = *(const float4*)(cen + base);
    float4 s4 = *(const float4*)(siz + base);
    float4 i4 = *(const float4*)(gio + base);
    const float* semRow = sem + ((long long)bq << 9);

    float cls[4];
    #pragma unroll
    for (int k = 0; k < 4; ++k) {
        int lb = g_lab[(b << 7) + g + k] & (CC - 1);
        float x = __ldg(semRow + lb);
        float p = 1.0f / (1.0f + expf(-x));
        float om = 1.0f - p;
        float pos = 0.25f * om * om * (-logf(p + 1e-8f));
        float neg = 0.75f * p * p * (-log1pf(-(p - 1e-8f)));
        cls[k] = pos - neg;
    }
    float4 o;
    o.x = 2.0f * cls[0] + 5.0f * c4.x + s4.x - 2.0f * i4.x;
    o.y = 2.0f * cls[1] + 5.0f * c4.y + s4.y - 2.0f * i4.y;
    o.z = 2.0f * cls[2] + 5.0f * c4.z + s4.z - 2.0f * i4.z;
    o.w = 2.0f * cls[3] + 5.0f * c4.w + s4.w - 2.0f * i4.w;
    *(float4*)(outCost + base) = o;
}

// ---------------------------------------------------------------------------
__global__ void transpose_kernel(const float* __restrict__ src) {
    __shared__ float tile[32][33];
    int b  = blockIdx.z;
    int q0 = blockIdx.x * 32;
    int g0 = blockIdx.y * 32;
    const float* s = src + (long long)b * QQ * GG;
    float* d = g_costT + (long long)b * QQ * GG;
    #pragma unroll
    for (int r = threadIdx.y; r < 32; r += 8)
        tile[r][threadIdx.x] = s[(q0 + r) * GG + g0 + threadIdx.x];
    __syncthreads();
    #pragma unroll
    for (int r = threadIdx.y; r < 32; r += 8)
        d[(g0 + r) * QQ + q0 + threadIdx.x] = tile[threadIdx.x][r];
}

// ---------------------------------------------------------------------------
// Top-K select: exact radix-descent threshold over distinct u64 keys covering
// [KCAND,256] smallest, compact, 256-wide bitonic sort. Rows g>=n[b] skipped.
// ---------------------------------------------------------------------------
__global__ void select_kernel() {
    int rowid = blockIdx.x;                  // b*GG + g
    int b = rowid >> 7, g = rowid & (GG - 1);
    int nb = g_n[b]; if (nb > GG) nb = GG;
    if (g >= nb) return;

    __shared__ unsigned int hist[256];
    __shared__ unsigned long long list[256];
    __shared__ unsigned long long s_boundary;
    __shared__ int s_pivot, s_cumIncl, s_cnt, s_countBelow;

    int t = threadIdx.x;
    const float* row = g_costT + (long long)rowid * QQ;
    unsigned long long k8[8];
    #pragma unroll
    for (int e = 0; e < 8; ++e) {
        int j = t + (e << 8);
        unsigned bits = __float_as_uint(row[j]);
        unsigned s = (bits & 0x80000000u) ? ~bits : (bits | 0x80000000u);
        k8[e] = ((unsigned long long)s << 32) | (unsigned)(j + 1);
    }
    if (t == 0) { s_countBelow = 0; s_cnt = 0; }
    unsigned long long prefix = 0;
    int shift = 56;
    __syncthreads();

    for (int level = 0; level < 8; ++level) {
        hist[t] = 0;
        __syncthreads();
        if (level == 0) {
            #pragma unroll
            for (int e = 0; e < 8; ++e) atomicAdd(&hist[(unsigned)(k8[e] >> 56)], 1u);
        } else {
            unsigned long long am = ~(((unsigned long long)1 << (shift + 8)) - 1);
            #pragma unroll
            for (int e = 0; e < 8; ++e)
                if ((k8[e] & am) == prefix)
                    atomicAdd(&hist[(unsigned)((k8[e] >> shift) & 255)], 1u);
        }
        __syncthreads();
        if (t < 32) {
            int c[8]; int s = 0;
            #pragma unroll
            for (int q = 0; q < 8; ++q) { c[q] = hist[t * 8 + q]; s += c[q]; }
            int incl = s;
            #pragma unroll
            for (int off = 1; off < 32; off <<= 1) {
                int o = __shfl_up_sync(0xffffffffu, incl, off);
                if (t >= off) incl += o;
            }
            int need = KCAND - s_countBelow;
            unsigned msk = __ballot_sync(0xffffffffu, incl >= need);
            int L = __ffs(msk) - 1;
            if (t == L) {
                int running = incl - s; int q;
                #pragma unroll
                for (q = 0; q < 8; ++q) { running += c[q]; if (running >= need) break; }
                s_pivot = t * 8 + q;
                s_cumIncl = running;
            }
        }
        __syncthreads();
        int pivot = s_pivot;
        int keep = s_countBelow + s_cumIncl;
        if (keep <= 256) {
            if (t == 0) {
                unsigned long long bnd = prefix + (((unsigned long long)(pivot + 1)) << shift);
                s_boundary = (bnd == 0) ? 0xFFFFFFFFFFFFFFFFULL : bnd;
            }
            __syncthreads();
            break;
        }
        if (t == 0) s_countBelow = keep - (int)hist[pivot];
        prefix |= ((unsigned long long)pivot) << shift;
        shift -= 8;
        __syncthreads();
    }

    unsigned long long bnd = s_boundary;
    int cnt = 0;
    #pragma unroll
    for (int e = 0; e < 8; ++e) cnt += (k8[e] < bnd) ? 1 : 0;
    int off = atomicAdd(&s_cnt, cnt);
    #pragma unroll
    for (int e = 0; e < 8; ++e)
        if (k8[e] < bnd) list[off++] = k8[e];
    __syncthreads();
    int K = s_cnt;
    if (t >= K) list[t] = 0xFFFFFFFFFFFFFFFFULL;
    __syncthreads();

    unsigned long long key = list[t];
    for (int k = 2; k <= 256; k <<= 1) {
        for (int j = k >> 1; j > 0; j >>= 1) {
            unsigned long long other;
            if (j >= 32) {
                list[t] = key; __syncthreads();
                other = list[t ^ j]; __syncthreads();
            } else {
                other = __shfl_xor_sync(0xffffffffu, key, j);
            }
            bool takeMin = (((t & j) == 0) == ((t & k) == 0));
            if (takeMin ? (other < key) : (other > key)) key = other;
        }
    }
    if (t < KCAND) g_cand[(long long)rowid * KCAND + t] = key;
}

// ---------------------------------------------------------------------------
__device__ __forceinline__ unsigned long long dsort(double x) {
    long long sb = __double_as_longlong(x);
    unsigned long long ub = (unsigned long long)sb;
    return (sb < 0) ? ~ub : (ub | 0x8000000000000000ULL);
}
__device__ __forceinline__ double dunsort(unsigned long long s) {
    unsigned long long ub = (s & 0x8000000000000000ULL) ? (s & 0x7FFFFFFFFFFFFFFFULL) : ~s;
    return __longlong_as_double((long long)ub);
}

struct LsaSmem1 {
    double u[GG + 2];
    unsigned long long cand[GG][64];     // first 64 sorted candidates per row
    float asgVals[GG][GG + 1];           // [slot][row], stride 129 conflict-free
    unsigned short p_[QQ + 2];
};

// -------- single-warp solver: one warp per batch, no __syncthreads ---------
// partB: lane owns slots lane+32k (k=0..3): v / excl / acc in registers.
// partA: first unassigned candidate == min key among unassigned (sorted keys).
// Joint min via 4 chained REDUX.MIN.U32: key-hi, key-lo, col tiebreak, row.
__global__ void lsa_kernel(void* __restrict__ outInds, float* __restrict__ outMask,
                           const float* __restrict__ outCost, int rawMode) {
    extern __shared__ char smemRaw[];
    LsaSmem1* S = (LsaSmem1*)smemRaw;
    int b = blockIdx.x, lane = threadIdx.x;
    int n = g_n[b]; if (n < 0) n = 0; if (n > GG) n = GG;
    const float* costB = outCost + (long long)b * QQ * GG;

    for (int j = lane; j <= QQ; j += 32) S->p_[j] = 0;
    for (int j = lane; j < GG + 2; j += 32) S->u[j] = 0.0;
    for (int r = 0; r < n; ++r) {
        const unsigned long long* gr = g_cand + (long long)(b * GG + r) * KCAND;
        ulonglong2 v2 = *(const ulonglong2*)(gr + 2 * lane);
        S->cand[r][2 * lane] = v2.x;
        S->cand[r][2 * lane + 1] = v2.y;
    }
    __syncwarp();

    double slotV[4], slotAcc[4];
    int slotMi[4];                        // (row<<16)|col
    unsigned actMask = 0, exclMask = 0;
    int freshK = -1;
    float prefVal = 0.0f;
    float4 pend4 = make_float4(0, 0, 0, 0);
    int pendSlot = -1;
    double rowAcc = 0.0;
    int i = 1, i0 = 1, asgCnt = 0;
    bool fresh = true;
    #pragma unroll
    for (int k = 0; k < 4; ++k) { slotV[k] = 0.0; slotAcc[k] = 0.0; slotMi[k] = 0; }

    if (n > 0) {
        for (;;) {
            // ========================= WORK =========================
            double ui = fresh ? 0.0 : S->u[i0];
            unsigned long long lkey = 0xFFFFFFFFFFFFFFFFULL;
            int lmi = 0x7fffffff;           // (row<<16)|col, col bits large
            #pragma unroll
            for (int k = 0; k < 4; ++k) {
                unsigned bit = 1u << k;
                if ((actMask & bit) && !(exclMask & bit)) {
                    float cv = (k == freshK) ? prefVal
                                             : S->asgVals[lane + 32 * k][i0 - 1];
                    double cur = ((double)cv - ui) - slotV[k];
                    unsigned long long kk = dsort(cur);
                    int mi = slotMi[k];
                    if (kk < lkey || (kk == lkey && (mi & 0xffff) < (lmi & 0xffff))) {
                        lkey = kk; lmi = mi;
                    }
                }
            }
            {   // partA
                int row = i0 - 1;
                unsigned long long c0 = S->cand[row][lane];
                unsigned long long c1 = S->cand[row][lane + 32];
                int ia0 = (int)(c0 & 0xffffffffu);
                int ia1 = (int)(c1 & 0xffffffffu);
                bool v0 = (S->p_[ia0] == 0);
                bool v1 = (S->p_[ia1] == 0);
                unsigned long long ac = v0 ? c0 : c1;
                int acol = v0 ? ia0 : ia1;
                bool av = v0 | v1;
                unsigned any = __ballot_sync(FULLM, av);
                if (!any) {
                    const unsigned long long* gr = g_cand + (long long)(b * GG + row) * KCAND;
                    av = false;
                    for (int bs = 64; bs < KCAND; bs += 32) {
                        int kk2 = bs + lane;
                        bool okf = false;
                        if (kk2 < KCAND) {
                            ac = gr[kk2];
                            acol = (int)(ac & 0xffffffffu);
                            okf = (S->p_[acol] == 0);
                        }
                        any = __ballot_sync(FULLM, okf);
                        if (any) { av = okf; break; }
                    }
                }
                if (av) {
                    unsigned sf = (unsigned)(ac >> 32);
                    unsigned fb2 = (sf & 0x80000000u) ? (sf & 0x7fffffffu) : ~sf;
                    double avd = (double)__uint_as_float(fb2) - ui;  // v==0 unassigned
                    unsigned long long ak = dsort(avd);
                    if (ak < lkey || (ak == lkey && acol < (lmi & 0xffff))) {
                        lkey = ak; lmi = acol;                        // row = 0 marker
                    }
                }
            }
            // ======================= REDUCE =========================
            unsigned hi = (unsigned)(lkey >> 32), lo = (unsigned)lkey;
            unsigned mh = __reduce_min_sync(FULLM, hi);
            unsigned lo2 = (hi == mh) ? lo : 0xffffffffu;
            unsigned ml = __reduce_min_sync(FULLM, lo2);
            bool km = (hi == mh) && (lo == ml);
            unsigned c2 = km ? (unsigned)(lmi & 0xffff) : 0xffffffffu;
            unsigned mc = __reduce_min_sync(FULLM, c2);
            unsigned r2 = (km && (unsigned)(lmi & 0xffff) == mc)
                              ? (unsigned)(lmi >> 16) : 0xffffffffu;
            unsigned mr = __reduce_min_sync(FULLM, r2);
            // ======================= MERGE ==========================
            freshK = -1;
            if (pendSlot >= 0) {           // column gather from prev assignment
                float* dst = &S->asgVals[pendSlot][4 * lane];
                dst[0] = pend4.x; dst[1] = pend4.y; dst[2] = pend4.z; dst[3] = pend4.w;
                pendSlot = -1;
            }
            unsigned long long bk = ((unsigned long long)mh << 32) | ml;
            int bcol = (int)mc, brow = (int)mr;
            double delta = dunsort(bk);
            rowAcc += delta;
            #pragma unroll
            for (int k = 0; k < 4; ++k)
                if (exclMask & (1u << k)) slotAcc[k] += delta;
            if (brow == 0) {
                // done: bcol unassigned -> assign to row i; flush duals
                #pragma unroll
                for (int k = 0; k < 4; ++k) {
                    if (exclMask & (1u << k)) {
                        slotV[k] -= slotAcc[k];
                        S->u[slotMi[k] >> 16] += slotAcc[k];
                        slotAcc[k] = 0.0;
                    }
                }
                exclMask = 0;
                if (lane == 0) { S->p_[bcol] = (unsigned short)i; S->u[i] += rowAcc; }
                if (lane == (asgCnt & 31)) {
                    int k = asgCnt >> 5;
                    actMask |= 1u << k;
                    slotV[k] = 0.0; slotAcc[k] = 0.0;
                    slotMi[k] = (i << 16) | bcol;
                    freshK = k;
                    if (i < n) prefVal = __ldg(costB + (long long)(bcol - 1) * GG + i);
                }
                pend4 = __ldg((const float4*)(costB + (long long)(bcol - 1) * GG) + lane);
                pendSlot = asgCnt;
                asgCnt++; i++; rowAcc = 0.0;
                if (i > n) break;
                i0 = i; fresh = true;
            } else {
                #pragma unroll
                for (int k = 0; k < 4; ++k) {
                    if ((actMask & (1u << k)) && (slotMi[k] & 0xffff) == bcol) {
                        exclMask |= 1u << k;
                        slotAcc[k] = 0.0;
                    }
                }
                i0 = brow; fresh = false;
            }
            __syncwarp();
        }
    }
    __syncwarp();

    for (int j = lane; j < QQ; j += 32) {
        int pi = S->p_[j + 1];
        int off = b * QQ + j;
        long long gi = pi > 0 ? (long long)(pi - 1) : 0;
        if (rawMode) ((long long*)outInds)[off] = gi;
        else         ((float*)outInds)[off] = (float)gi;
        outMask[off] = pi > 0 ? 1.0f : 0.0f;
    }
}

// ---------------------------------------------------------------------------
extern "C" void kernel_launch(void* const* d_in, const int* in_sizes, int n_in,
                              void* d_out, int out_size) {
    const float* sem = (const float*)d_in[0];
    const float* cen = (const float*)d_in[1];
    const float* siz = (const float*)d_in[2];
    const float* gio = (const float*)d_in[3];
    const void*  lab = d_in[4];
    const void*  na  = d_in[5];

    int rawMode = (out_size == 2146304) ? 1 : 0;
    void*  outInds;
    float* outMask;
    float* outCost;
    if (rawMode) {
        outInds = d_out;
        outMask = (float*)((char*)d_out + (size_t)BB * QQ * 8);
        outCost = (float*)((char*)d_out + (size_t)BB * QQ * 8 + (size_t)BB * QQ * 4);
    } else {
        outInds = d_out;
        outMask = (float*)d_out + BB * QQ;
        outCost = (float*)d_out + 2 * BB * QQ;
    }

    cudaFuncSetAttribute(lsa_kernel, cudaFuncAttributeMaxDynamicSharedMemorySize,
                         (int)sizeof(LsaSmem1));

    prep_kernel<<<1, 1024>>>(lab, na);
    cost_kernel<<<(BB * QQ * GG) / (256 * 4), 256>>>(sem, cen, siz, gio, outCost);
    transpose_kernel<<<dim3(QQ / 32, GG / 32, BB), dim3(32, 8)>>>(outCost);
    select_kernel<<<BB * GG, 256>>>();
    lsa_kernel<<<BB, 32, sizeof(LsaSmem1)>>>(outInds, outMask, outCost, rawMode);
}

// round 15
// speedup vs baseline: 1.3599x; 1.3599x over previous
#include <cuda_runtime.h>
#include <cuda_bf16.h>

#define BB 8
#define QQ 2048
#define GG 128
#define CC 512
#define KCAND 144
#define LSA_THREADS 160
#define FULLM 0xffffffffu

// ---------------- global scratch ----------------
__device__ float g_costT[BB * GG * QQ];                    // [b][g][q]
__device__ unsigned long long g_cand[BB * GG * KCAND];     // sorted (val,idx) per row
__device__ int g_lab[BB * GG];
__device__ int g_n[BB];

// ---------------------------------------------------------------------------
__global__ void prep_kernel(const void* __restrict__ lab, const void* __restrict__ na) {
    __shared__ int s_bad;
    int t = threadIdx.x;
    if (t == 0) s_bad = 0;
    __syncthreads();
    if (t < 512) {
        long long v = ((const long long*)lab)[t];
        if (v < 0 || v >= CC) s_bad = 1;   // benign race, same value
    }
    __syncthreads();
    if (s_bad == 0) {
        if (t < BB * GG) g_lab[t] = (int)((const long long*)lab)[t];
        if (t < BB)      g_n[t]   = (int)((const long long*)na)[t];
    } else {
        if (t < BB * GG) g_lab[t] = ((const int*)lab)[t];
        if (t < BB)      g_n[t]   = ((const int*)na)[t];
    }
}

// ---------------------------------------------------------------------------
__global__ void cost_kernel(const float* __restrict__ sem,
                            const float* __restrict__ cen,
                            const float* __restrict__ siz,
                            const float* __restrict__ gio,
                            float* __restrict__ outCost) {
    int tid  = blockIdx.x * blockDim.x + threadIdx.x;
    int base = tid << 2;
    if (base >= BB * QQ * GG) return;
    int g  = base & (GG - 1);
    int bq = base >> 7;
    int b  = bq >> 11;

    float4 c4 = *(const float4*)(cen + base);
    float4 s4 = *(const float4*)(siz + base);
    float4 i4 = *(const float4*)(gio + base);
    const float* semRow = sem + ((long long)bq << 9);

    float cls[4];
    #pragma unroll
    for (int k = 0; k < 4; ++k) {
        int lb = g_lab[(b << 7) + g + k] & (CC - 1);
        float x = __ldg(semRow + lb);
        float p = 1.0f / (1.0f + expf(-x));
        float om = 1.0f - p;
        float pos = 0.25f * om * om * (-logf(p + 1e-8f));
        float neg = 0.75f * p * p * (-log1pf(-(p - 1e-8f)));
        cls[k] = pos - neg;
    }
    float4 o;
    o.x = 2.0f * cls[0] + 5.0f * c4.x + s4.x - 2.0f * i4.x;
    o.y = 2.0f * cls[1] + 5.0f * c4.y + s4.y - 2.0f * i4.y;
    o.z = 2.0f * cls[2] + 5.0f * c4.z + s4.z - 2.0f * i4.z;
    o.w = 2.0f * cls[3] + 5.0f * c4.w + s4.w - 2.0f * i4.w;
    *(float4*)(outCost + base) = o;
}

// ---------------------------------------------------------------------------
__global__ void transpose_kernel(const float* __restrict__ src) {
    __shared__ float tile[32][33];
    int b  = blockIdx.z;
    int q0 = blockIdx.x * 32;
    int g0 = blockIdx.y * 32;
    const float* s = src + (long long)b * QQ * GG;
    float* d = g_costT + (long long)b * QQ * GG;
    #pragma unroll
    for (int r = threadIdx.y; r < 32; r += 8)
        tile[r][threadIdx.x] = s[(q0 + r) * GG + g0 + threadIdx.x];
    __syncthreads();
    #pragma unroll
    for (int r = threadIdx.y; r < 32; r += 8)
        d[(g0 + r) * QQ + q0 + threadIdx.x] = tile[threadIdx.x][r];
}

// ---------------------------------------------------------------------------
// Top-K select (unchanged from measured-good R5 version).
// ---------------------------------------------------------------------------
__global__ void select_kernel() {
    int rowid = blockIdx.x;                  // b*GG + g
    int b = rowid >> 7, g = rowid & (GG - 1);
    int nb = g_n[b]; if (nb > GG) nb = GG;
    if (g >= nb) return;

    __shared__ unsigned int hist[256];
    __shared__ unsigned long long list[256];
    __shared__ unsigned long long s_boundary;
    __shared__ int s_pivot, s_cumIncl, s_cnt, s_countBelow;

    int t = threadIdx.x;
    const float* row = g_costT + (long long)rowid * QQ;
    unsigned long long k8[8];
    #pragma unroll
    for (int e = 0; e < 8; ++e) {
        int j = t + (e << 8);
        unsigned bits = __float_as_uint(row[j]);
        unsigned s = (bits & 0x80000000u) ? ~bits : (bits | 0x80000000u);
        k8[e] = ((unsigned long long)s << 32) | (unsigned)(j + 1);
    }
    if (t == 0) { s_countBelow = 0; s_cnt = 0; }
    unsigned long long prefix = 0;
    int shift = 56;
    __syncthreads();

    for (int level = 0; level < 8; ++level) {
        hist[t] = 0;
        __syncthreads();
        if (level == 0) {
            #pragma unroll
            for (int e = 0; e < 8; ++e) atomicAdd(&hist[(unsigned)(k8[e] >> 56)], 1u);
        } else {
            unsigned long long am = ~(((unsigned long long)1 << (shift + 8)) - 1);
            #pragma unroll
            for (int e = 0; e < 8; ++e)
                if ((k8[e] & am) == prefix)
                    atomicAdd(&hist[(unsigned)((k8[e] >> shift) & 255)], 1u);
        }
        __syncthreads();
        if (t < 32) {
            int c[8]; int s = 0;
            #pragma unroll
            for (int q = 0; q < 8; ++q) { c[q] = hist[t * 8 + q]; s += c[q]; }
            int incl = s;
            #pragma unroll
            for (int off = 1; off < 32; off <<= 1) {
                int o = __shfl_up_sync(0xffffffffu, incl, off);
                if (t >= off) incl += o;
            }
            int need = KCAND - s_countBelow;
            unsigned msk = __ballot_sync(0xffffffffu, incl >= need);
            int L = __ffs(msk) - 1;
            if (t == L) {
                int running = incl - s; int q;
                #pragma unroll
                for (q = 0; q < 8; ++q) { running += c[q]; if (running >= need) break; }
                s_pivot = t * 8 + q;
                s_cumIncl = running;
            }
        }
        __syncthreads();
        int pivot = s_pivot;
        int keep = s_countBelow + s_cumIncl;
        if (keep <= 256) {
            if (t == 0) {
                unsigned long long bnd = prefix + (((unsigned long long)(pivot + 1)) << shift);
                s_boundary = (bnd == 0) ? 0xFFFFFFFFFFFFFFFFULL : bnd;
            }
            __syncthreads();
            break;
        }
        if (t == 0) s_countBelow = keep - (int)hist[pivot];
        prefix |= ((unsigned long long)pivot) << shift;
        shift -= 8;
        __syncthreads();
    }

    unsigned long long bnd = s_boundary;
    int cnt = 0;
    #pragma unroll
    for (int e = 0; e < 8; ++e) cnt += (k8[e] < bnd) ? 1 : 0;
    int off = atomicAdd(&s_cnt, cnt);
    #pragma unroll
    for (int e = 0; e < 8; ++e)
        if (k8[e] < bnd) list[off++] = k8[e];
    __syncthreads();
    int K = s_cnt;
    if (t >= K) list[t] = 0xFFFFFFFFFFFFFFFFULL;
    __syncthreads();

    unsigned long long key = list[t];
    for (int k = 2; k <= 256; k <<= 1) {
        for (int j = k >> 1; j > 0; j >>= 1) {
            unsigned long long other;
            if (j >= 32) {
                list[t] = key; __syncthreads();
                other = list[t ^ j]; __syncthreads();
            } else {
                other = __shfl_xor_sync(0xffffffffu, key, j);
            }
            bool takeMin = (((t & j) == 0) == ((t & k) == 0));
            if (takeMin ? (other < key) : (other > key)) key = other;
        }
    }
    if (t < KCAND) g_cand[(long long)rowid * KCAND + t] = key;
}

// ---------------------------------------------------------------------------
__device__ __forceinline__ unsigned long long dsort(double x) {
    long long sb = __double_as_longlong(x);
    unsigned long long ub = (unsigned long long)sb;
    return (sb < 0) ? ~ub : (ub | 0x8000000000000000ULL);
}

struct LsaSmem {
    double u[GG + 2];
    unsigned long long bkey[2][4];
    int bidx[2][4];
    double bcv[2][4];                    // winner's cached cost (double)
    double bsv[2][4];                    // winner's v
    unsigned long long aPacked[2];
    unsigned long long cand[GG][64];     // first 64 sorted candidates per row
    double asgVals[GG][GG + 1];          // [slot][row] as double
    unsigned short p_[QQ + 1];
};

// 160 threads: 4 partB warps (1 slot/lane) + 1 partA warp. One bar per iter.
// Compare keys are u-free (uniform shift doesn't change argmin); exact
// reference delta fl(fl(C-u)-v) is computed post-selection from the winner's
// published (cv, v) and prefetched u[i0] — off the selection critical path.
__global__ void lsa_kernel(void* __restrict__ outInds, float* __restrict__ outMask,
                           const float* __restrict__ outCost, int rawMode) {
    extern __shared__ char smemRaw[];
    LsaSmem* S = (LsaSmem*)smemRaw;
    int b = blockIdx.x, t = threadIdx.x;
    int warp = t >> 5, lane = t & 31;
    int n = g_n[b]; if (n < 0) n = 0; if (n > GG) n = GG;
    const float* costB = outCost + (long long)b * QQ * GG;

    for (int j = t; j <= QQ; j += LSA_THREADS) S->p_[j] = 0;
    for (int j = t; j < GG + 2; j += LSA_THREADS) S->u[j] = 0.0;
    for (int idx = t; idx < GG * 64; idx += LSA_THREADS) {
        int r = idx >> 6, k = idx & 63;
        S->cand[r][k] = g_cand[(long long)(b * GG + r) * KCAND + k];
    }
    __syncthreads();

    double myV = 0.0, myAcc = 0.0, rowAcc = 0.0, prefD = 0.0;
    int myCol = -1, myRow = 0;
    bool myActive = false, myExcl = false, myFresh = false;
    float pendVal = 0.0f; int pendSlot = -1;
    int i = 1, i0 = 1, asgCnt = 0, bjLast = -1, par = 0;
    bool fresh = true;

    if (n > 0) {
        for (;;) {
            // ========================= WORK =========================
            double uiPre = fresh ? 0.0 : S->u[i0];    // only used for delta in merge
            if (t < 128) {
                unsigned long long mk = 0xFFFFFFFFFFFFFFFFULL;
                int mi = 0x7fffffff;
                double mycv = 0.0, mysv = 0.0;
                if (myActive && !myExcl) {
                    double cvd = myFresh ? prefD : S->asgVals[t][i0 - 1];
                    double cur = cvd - myV;            // u-free compare key
                    mk = dsort(cur); mi = (myRow << 16) | myCol;
                    mycv = cvd; mysv = myV;
                }
                if (pendSlot >= 0) { S->asgVals[pendSlot][t] = (double)pendVal; pendSlot = -1; }
                // REDUX-based intra-warp argmin on (key, col)
                unsigned hi = (unsigned)(mk >> 32), lo = (unsigned)mk;
                unsigned mh = __reduce_min_sync(FULLM, hi);
                unsigned lo2 = (hi == mh) ? lo : 0xffffffffu;
                unsigned ml = __reduce_min_sync(FULLM, lo2);
                bool match = (hi == mh) && (lo == ml);
                unsigned bal = __ballot_sync(FULLM, match);
                if (__popc(bal) > 1) {                 // rare exact-tie fallback
                    unsigned c2 = match ? (unsigned)(mi & 0xffff) : 0xffffffffu;
                    unsigned mc2 = __reduce_min_sync(FULLM, c2);
                    bal = __ballot_sync(FULLM, match && ((unsigned)(mi & 0xffff) == mc2));
                }
                int wl = __ffs(bal) - 1;
                if (lane == wl) {
                    S->bkey[par][warp] = mk; S->bidx[par][warp] = mi;
                    S->bcv[par][warp] = mycv; S->bsv[par][warp] = mysv;
                }
            } else {
                // partA: first unassigned candidate in rank order (0-31 then 32-63)
                int row = i0 - 1;
                unsigned long long c0 = S->cand[row][lane];
                unsigned long long c1 = S->cand[row][lane + 32];
                int ia0 = (int)(c0 & 0xffffffffu);
                int ia1 = (int)(c1 & 0xffffffffu);
                bool f0 = (S->p_[ia0] == 0) && (ia0 != bjLast);
                unsigned m0 = __ballot_sync(FULLM, f0);
                unsigned long long ac;
                if (m0) {
                    ac = __shfl_sync(FULLM, c0, __ffs(m0) - 1);
                } else {
                    bool f1 = (S->p_[ia1] == 0) && (ia1 != bjLast);
                    unsigned m1 = __ballot_sync(FULLM, f1);
                    if (m1) {
                        ac = __shfl_sync(FULLM, c1, __ffs(m1) - 1);
                    } else {
                        const unsigned long long* gr =
                            g_cand + (long long)(b * GG + row) * KCAND;
                        ac = 0;
                        for (int bs = 64; bs < KCAND; bs += 32) {
                            int kk = bs + lane;
                            unsigned long long cf = 0; bool okf = false;
                            if (kk < KCAND) {
                                cf = gr[kk];
                                int ci = (int)(cf & 0xffffffffu);
                                okf = (S->p_[ci] == 0) && (ci != bjLast);
                            }
                            unsigned mf = __ballot_sync(FULLM, okf);
                            if (mf) { ac = __shfl_sync(FULLM, cf, __ffs(mf) - 1); break; }
                        }
                    }
                }
                if (lane == 0) S->aPacked[par] = ac;
            }
            __syncthreads();
            // ======================= MERGE (redundant) =======================
            bool wasFresh = myFresh;
            unsigned long long ap = S->aPacked[par];
            unsigned sf = (unsigned)(ap >> 32);
            unsigned fb = (sf & 0x80000000u) ? (sf & 0x7fffffffu) : ~sf;
            float af = __uint_as_float(fb);
            unsigned long long bk = dsort((double)af);   // u-free key, v==0
            int bcol = (int)(ap & 0xffffffffu);
            int brow = 0, bw = -1;
            #pragma unroll
            for (int w2 = 0; w2 < 4; ++w2) {
                unsigned long long wk = S->bkey[par][w2]; int wi = S->bidx[par][w2];
                int wc = wi & 0xffff;
                if (wk < bk || (wk == bk && wc < bcol)) {
                    bk = wk; bcol = wc; brow = wi >> 16; bw = w2;
                }
            }
            double cvd = (bw < 0) ? (double)af : S->bcv[par][bw];
            double svv = (bw < 0) ? 0.0 : S->bsv[par][bw];
            par ^= 1;
            double delta = (cvd - uiPre) - svv;          // exact reference delta
            rowAcc += delta;
            if (myExcl) myAcc += delta;
            if (brow == 0) {
                // done: bcol unassigned -> assign to row i; flush duals
                if (myExcl) { myV -= myAcc; S->u[myRow] += myAcc; myExcl = false; myAcc = 0.0; }
                if (t == 0) { S->p_[bcol] = (unsigned short)i; S->u[i] += rowAcc; }
                if (t == asgCnt) {
                    myActive = true; myCol = bcol; myRow = i;
                    myV = 0.0; myAcc = 0.0; myExcl = false; myFresh = true;
                    if (i < n) prefD = (double)__ldg(costB + (long long)(bcol - 1) * GG + i);
                }
                if (t < GG) {
                    pendVal = __ldg(costB + (long long)(bcol - 1) * GG + t);
                    pendSlot = asgCnt;
                }
                asgCnt++; bjLast = bcol; i++; rowAcc = 0.0;
                if (i > n) break;
                i0 = i; fresh = true;
            } else {
                if (myActive && myCol == bcol) { myExcl = true; myAcc = 0.0; }
                i0 = brow; fresh = false; bjLast = -1;
            }
            if (wasFresh) myFresh = false;
        }
    }
    __syncthreads();

    for (int j = t; j < QQ; j += LSA_THREADS) {
        int pi = S->p_[j + 1];
        int off = b * QQ + j;
        long long gi = pi > 0 ? (long long)(pi - 1) : 0;
        if (rawMode) ((long long*)outInds)[off] = gi;
        else         ((float*)outInds)[off] = (float)gi;
        outMask[off] = pi > 0 ? 1.0f : 0.0f;
    }
}

// ---------------------------------------------------------------------------
extern "C" void kernel_launch(void* const* d_in, const int* in_sizes, int n_in,
                              void* d_out, int out_size) {
    const float* sem = (const float*)d_in[0];
    const float* cen = (const float*)d_in[1];
    const float* siz = (const float*)d_in[2];
    const float* gio = (const float*)d_in[3];
    const void*  lab = d_in[4];
    const void*  na  = d_in[5];

    int rawMode = (out_size == 2146304) ? 1 : 0;
    void*  outInds;
    float* outMask;
    float* outCost;
    if (rawMode) {
        outInds = d_out;
        outMask = (float*)((char*)d_out + (size_t)BB * QQ * 8);
        outCost = (float*)((char*)d_out + (size_t)BB * QQ * 8 + (size_t)BB * QQ * 4);
    } else {
        outInds = d_out;
        outMask = (float*)d_out + BB * QQ;
        outCost = (float*)d_out + 2 * BB * QQ;
    }

    cudaFuncSetAttribute(lsa_kernel, cudaFuncAttributeMaxDynamicSharedMemorySize,
                         (int)sizeof(LsaSmem));

    prep_kernel<<<1, 1024>>>(lab, na);
    cost_kernel<<<(BB * QQ * GG) / (256 * 4), 256>>>(sem, cen, siz, gio, outCost);
    transpose_kernel<<<dim3(QQ / 32, GG / 32, BB), dim3(32, 8)>>>(outCost);
    select_kernel<<<BB * GG, 256>>>();
    lsa_kernel<<<BB, LSA_THREADS, sizeof(LsaSmem)>>>(outInds, outMask, outCost, rawMode);
}